// round 2
// baseline (speedup 1.0000x reference)
#include <cuda_runtime.h>
#include <math.h>

#define BB 8
#define NN 2048
#define NP 512
#define KW 16
#define ROWS (BB*NP*KW)   // 65536

// ---------------- scratch (static device globals; no allocation) ----------------
__device__ int   d_fidx[BB*NP];
__device__ int   d_knn[ROWS];
__device__ float d_pp[BB*NN];
__device__ float d_geom[ROWS*10];
__device__ float d_S[3*ROWS*8];
__device__ float d_F0[ROWS*64];
__device__ float d_O0[ROWS*64];
__device__ float d_O1[ROWS*128];
__device__ float d_O2[ROWS*256];
__device__ float d_part[256*256*2];
__device__ float d_ab[512];

// ---------------- point squared norms ----------------
__global__ void pp_kernel(const float* __restrict__ xyz){
    int i = blockIdx.x*256 + threadIdx.x;
    if (i < BB*NN){
        int b = i / NN, n = i % NN;
        const float* X = xyz + b*3*NN;
        float x = X[n], y = X[NN+n], z = X[2*NN+n];
        d_pp[i] = __fadd_rn(__fadd_rn(__fmul_rn(x,x),__fmul_rn(y,y)),__fmul_rn(z,z));
    }
}

// ---------------- farthest point sampling (one block per batch) ----------------
__global__ void fps_kernel(const float* __restrict__ xyz, float* __restrict__ out){
    int b = blockIdx.x, tid = threadIdx.x;
    __shared__ float sx[NN], sy[NN], sz[NN];
    __shared__ float swv[8]; __shared__ int swi[8];
    __shared__ int sfid[NP];
    const float* X = xyz + b*3*NN;
    for (int i = tid; i < NN; i += 256){ sx[i]=X[i]; sy[i]=X[NN+i]; sz[i]=X[2*NN+i]; }
    float dist[8];
    #pragma unroll
    for (int j=0;j<8;j++) dist[j] = 1e10f;
    __syncthreads();
    int far = 0;
    for (int it = 0; it < NP; ++it){
        if (tid == 0) sfid[it] = far;
        float cx = sx[far], cy = sy[far], cz = sz[far];
        float bv = -1.f; int bi = 0x7fffffff;
        #pragma unroll
        for (int j=0;j<8;j++){
            int n = j*256 + tid;
            float dx = __fsub_rn(sx[n],cx), dy = __fsub_rn(sy[n],cy), dz = __fsub_rn(sz[n],cz);
            float d  = __fadd_rn(__fadd_rn(__fmul_rn(dx,dx),__fmul_rn(dy,dy)),__fmul_rn(dz,dz));
            d = fminf(dist[j], d);
            dist[j] = d;
            if (d > bv) { bv = d; bi = n; }   // ascending n -> strict > keeps first max
        }
        #pragma unroll
        for (int off=16; off; off>>=1){
            float v2 = __shfl_down_sync(0xffffffffu, bv, off);
            int   i2 = __shfl_down_sync(0xffffffffu, bi, off);
            if (v2 > bv || (v2 == bv && i2 < bi)) { bv = v2; bi = i2; }
        }
        if ((tid & 31) == 0){ swv[tid>>5] = bv; swi[tid>>5] = bi; }
        __syncthreads();
        float fv = swv[0]; int fi = swi[0];
        #pragma unroll
        for (int w=1; w<8; w++){
            float v2 = swv[w]; int i2 = swi[w];
            if (v2 > fv || (v2 == fv && i2 < fi)) { fv = v2; fi = i2; }
        }
        far = fi;
        __syncthreads();
    }
    for (int p = tid; p < NP; p += 256){
        int n = sfid[p];
        d_fidx[b*NP + p] = n;
        out[(b*3+0)*NP + p] = sx[n];
        out[(b*3+1)*NP + p] = sy[n];
        out[(b*3+2)*NP + p] = sz[n];
    }
}

// ---------------- KNN: one warp per query, top-16 ascending (d, idx) ----------------
__global__ void knn_kernel(const float* __restrict__ xyz){
    int gw   = (blockIdx.x*blockDim.x + threadIdx.x) >> 5;
    int lane = threadIdx.x & 31;
    int b = gw >> 9, p = gw & 511;
    int qi = d_fidx[b*NP + p];
    const float* X = xyz + b*3*NN;
    float qx = X[qi], qy = X[NN+qi], qz = X[2*NN+qi];
    float qq = d_pp[b*NN + qi];
    float dk[16]; int ik[16];
    #pragma unroll
    for (int j=0;j<16;j++){ dk[j] = 3.4e38f; ik[j] = 0x7fffffff; }
    for (int c = 0; c < NN/32; c++){
        int n = c*32 + lane;
        float bx = X[n], by = X[NN+n], bz = X[2*NN+n];
        float d = (qq + d_pp[b*NN + n]) - 2.0f*(qx*bx + qy*by + qz*bz);
        bool acc = (d < dk[15]) || (d == dk[15] && n < ik[15]);
        if (acc){
            int pos = 0;
            #pragma unroll
            for (int j=0;j<16;j++) pos += ((dk[j] < d) || (dk[j] == d && ik[j] < n)) ? 1 : 0;
            #pragma unroll
            for (int j=15;j>=0;--j){
                if (j > pos){ dk[j] = dk[j-1]; ik[j] = ik[j-1]; }
                else if (j == pos){ dk[j] = d; ik[j] = n; }
            }
        }
    }
    for (int r = 0; r < 16; r++){
        float v = dk[0]; int i = ik[0];
        #pragma unroll
        for (int off=16; off; off>>=1){
            float v2 = __shfl_xor_sync(0xffffffffu, v, off);
            int   i2 = __shfl_xor_sync(0xffffffffu, i, off);
            if (v2 < v || (v2 == v && i2 < i)) { v = v2; i = i2; }
        }
        if (lane == 0) d_knn[gw*16 + r] = i;
        if (ik[0] == i){
            #pragma unroll
            for (int j=0;j<15;j++){ dk[j] = dk[j+1]; ik[j] = ik[j+1]; }
            dk[15] = 3.4e38f; ik[15] = 0x7fffffff;
        }
    }
}

// ---------------- geometry features + feat gather + norm/X/Y outputs ----------------
__global__ void geom_kernel(const float* __restrict__ xyz, const float* __restrict__ nr,
                            const float* __restrict__ Xa, const float* __restrict__ Ya,
                            const float* __restrict__ pts, float* out){
    int idx = blockIdx.x*128 + threadIdx.x;  // 65536 rows
    int b = idx >> 13;
    int p = (idx >> 4) & 511;
    int k = idx & 15;
    int n = d_knn[idx];
    int base = b*3*NN;
    float cx = out[(b*3+0)*NP + p], cy = out[(b*3+1)*NP + p], cz = out[(b*3+2)*NP + p];
    float gx = xyz[base+n] - cx, gy = xyz[base+NN+n] - cy, gz = xyz[base+2*NN+n] - cz;
    float nxv = nr[base+n], nyv = nr[base+NN+n], nzv = nr[base+2*NN+n];
    float Xx = Xa[base+n], Xy = Xa[base+NN+n], Xz = Xa[base+2*NN+n];
    float Yx = Ya[base+n], Yy = Ya[base+NN+n], Yz = Ya[base+2*NN+n];
    float dsq  = gx*gx + gy*gy + gz*gz;
    float dist = sqrtf(dsq + 1e-10f);
    float dmin = dist, dmax = dist;
    #pragma unroll
    for (int off=8; off; off>>=1){
        dmin = fminf(dmin, __shfl_xor_sync(0xffffffffu, dmin, off, 16));
        dmax = fmaxf(dmax, __shfl_xor_sync(0xffffffffu, dmax, off, 16));
    }
    float dn  = (dist - dmin) / ((dmax - dmin) + 1e-10f);
    float nn2 = sqrtf(gx*gx + gy*gy + gz*gz);
    const float INVPI = 0.318309886183790671f;
    float a0, a1, a2;
    {
        float dot = gx*nxv + gy*nyv + gz*nzv;
        float vn  = sqrtf(nxv*nxv + nyv*nyv + nzv*nzv);
        float c1  = dot / (nn2*vn + 1e-8f);
        a0 = acosf(fminf(1.f, fmaxf(-1.f, c1))) * INVPI;
    }
    {
        float dot = gx*Xx + gy*Xy + gz*Xz;
        float vn  = sqrtf(Xx*Xx + Xy*Xy + Xz*Xz);
        float c1  = dot / (nn2*vn + 1e-8f);
        a1 = acosf(fminf(1.f, fmaxf(-1.f, c1))) * INVPI;
    }
    {
        float dot = gx*Yx + gy*Yy + gz*Yz;
        float vn  = sqrtf(Yx*Yx + Yy*Yy + Yz*Yz);
        float c1  = dot / (nn2*vn + 1e-8f);
        a2 = acosf(fminf(1.f, fmaxf(-1.f, c1))) * INVPI;
    }
    float* g = d_geom + idx*10;
    g[0]=gx; g[1]=gy; g[2]=gz; g[3]=dn; g[4]=nxv; g[5]=nyv; g[6]=nzv; g[7]=a0; g[8]=a1; g[9]=a2;
    const float* P = pts + b*64*NN;
    float* F = d_F0 + idx*64;
    #pragma unroll 8
    for (int c=0;c<64;c++) F[c] = P[c*NN + n];
    if (k == 0){
        int o1 = 3*BB*NP;  // 12288
        out[1*o1 + (b*3+0)*NP+p] = nxv; out[1*o1 + (b*3+1)*NP+p] = nyv; out[1*o1 + (b*3+2)*NP+p] = nzv;
        out[2*o1 + (b*3+0)*NP+p] = Xx;  out[2*o1 + (b*3+1)*NP+p] = Xy;  out[2*o1 + (b*3+2)*NP+p] = Xz;
        out[3*o1 + (b*3+0)*NP+p] = Yx;  out[3*o1 + (b*3+1)*NP+p] = Yy;  out[3*o1 + (b*3+2)*NP+p] = Yz;
    }
}

// ---------------- scores s = softmax(w2 relu(w1 g + b1) + b2), all 3 layers ----------------
__global__ void s_kernel(const float* __restrict__ w1_0, const float* __restrict__ b1_0,
                         const float* __restrict__ w2_0, const float* __restrict__ b2_0,
                         const float* __restrict__ w1_1, const float* __restrict__ b1_1,
                         const float* __restrict__ w2_1, const float* __restrict__ b2_1,
                         const float* __restrict__ w1_2, const float* __restrict__ b1_2,
                         const float* __restrict__ w2_2, const float* __restrict__ b2_2){
    int idx = blockIdx.x*256 + threadIdx.x;  // 65536
    float g[10];
    #pragma unroll
    for (int i=0;i<10;i++) g[i] = d_geom[idx*10 + i];
    const float* W1[3] = {w1_0, w1_1, w1_2};
    const float* B1[3] = {b1_0, b1_1, b1_2};
    const float* W2[3] = {w2_0, w2_1, w2_2};
    const float* B2[3] = {b2_0, b2_1, b2_2};
    #pragma unroll
    for (int l=0;l<3;l++){
        float h[16];
        #pragma unroll
        for (int j=0;j<16;j++){
            float acc = B1[l][j];
            #pragma unroll
            for (int q=0;q<10;q++) acc = fmaf(W1[l][j*10+q], g[q], acc);
            h[j] = fmaxf(acc, 0.f);
        }
        float t[8]; float mx = -3.4e38f;
        #pragma unroll
        for (int m=0;m<8;m++){
            float acc = B2[l][m];
            #pragma unroll
            for (int j=0;j<16;j++) acc = fmaf(W2[l][m*16+j], h[j], acc);
            t[m] = acc; mx = fmaxf(mx, acc);
        }
        float sum = 0.f;
        #pragma unroll
        for (int m=0;m<8;m++){ t[m] = expf(t[m] - mx); sum += t[m]; }
        float inv = 1.f / sum;
        #pragma unroll
        for (int m=0;m<8;m++) d_S[l*ROWS*8 + idx*8 + m] = t[m]*inv;
    }
}

// ---------------- PAConv GEMM: C[row,o] = sum_{m,c} s[row,m] F[row,c] bank[m,c,o] ----------------
template<int CIN, int COUT, bool USE_BN>
__global__ void __launch_bounds__(256) paconv_gemm(const float* __restrict__ F,
        const float* __restrict__ S, const float* __restrict__ bank,
        const float* __restrict__ ab, float* __restrict__ O){
    __shared__ float As[16*65];
    __shared__ float Bs[16*64];
    int row0 = blockIdx.y * 64;
    int col0 = blockIdx.x * 64;
    int tid  = threadIdx.x;
    int tx = tid & 15, ty = tid >> 4;
    int ta = tid & 15, ra = tid >> 4;
    int ob = tid & 63, tb = tid >> 6;
    float acc[4][4];
    #pragma unroll
    for (int i=0;i<4;i++)
        #pragma unroll
        for (int j=0;j<4;j++) acc[i][j] = 0.f;
    for (int kk = 0; kk < 8*CIN; kk += 16){
        int m  = kk / CIN;
        int c0 = kk % CIN;
        #pragma unroll
        for (int i=0;i<4;i++){
            int grow = row0 + ra + i*16;
            float v = F[grow*CIN + c0 + ta];
            if (USE_BN) v = fmaxf(fmaf(v, ab[c0+ta], ab[256 + c0+ta]), 0.f);
            As[ta*65 + ra + i*16] = S[grow*8 + m] * v;
        }
        #pragma unroll
        for (int i=0;i<4;i++){
            int t = tb + i*4;
            Bs[t*64 + ob] = bank[(m*CIN + c0 + t)*COUT + col0 + ob];
        }
        __syncthreads();
        #pragma unroll
        for (int t=0;t<16;t++){
            float a0 = As[t*65 + ty*4+0];
            float a1 = As[t*65 + ty*4+1];
            float a2 = As[t*65 + ty*4+2];
            float a3 = As[t*65 + ty*4+3];
            float4 bq = *(const float4*)&Bs[t*64 + tx*4];
            acc[0][0] = fmaf(a0, bq.x, acc[0][0]); acc[0][1] = fmaf(a0, bq.y, acc[0][1]);
            acc[0][2] = fmaf(a0, bq.z, acc[0][2]); acc[0][3] = fmaf(a0, bq.w, acc[0][3]);
            acc[1][0] = fmaf(a1, bq.x, acc[1][0]); acc[1][1] = fmaf(a1, bq.y, acc[1][1]);
            acc[1][2] = fmaf(a1, bq.z, acc[1][2]); acc[1][3] = fmaf(a1, bq.w, acc[1][3]);
            acc[2][0] = fmaf(a2, bq.x, acc[2][0]); acc[2][1] = fmaf(a2, bq.y, acc[2][1]);
            acc[2][2] = fmaf(a2, bq.z, acc[2][2]); acc[2][3] = fmaf(a2, bq.w, acc[2][3]);
            acc[3][0] = fmaf(a3, bq.x, acc[3][0]); acc[3][1] = fmaf(a3, bq.y, acc[3][1]);
            acc[3][2] = fmaf(a3, bq.z, acc[3][2]); acc[3][3] = fmaf(a3, bq.w, acc[3][3]);
        }
        __syncthreads();
    }
    #pragma unroll
    for (int i=0;i<4;i++)
        #pragma unroll
        for (int j=0;j<4;j++)
            O[(row0 + ty*4 + i)*COUT + col0 + tx*4 + j] = acc[i][j];
}

// ---------------- BN stats: deterministic two-stage ----------------
template<int C>
__global__ void bn_stats1(const float* __restrict__ O){
    __shared__ float sm1[256], sm2[256];
    int tid = threadIdx.x;
    float s1 = 0.f, s2 = 0.f;
    for (int i = blockIdx.x*256 + tid; i < ROWS*C; i += 65536){
        float v = O[i]; s1 += v; s2 += v*v;
    }
    sm1[tid] = s1; sm2[tid] = s2; __syncthreads();
    if (tid < C){
        for (int j = tid + C; j < 256; j += C){ s1 += sm1[j]; s2 += sm2[j]; }
        d_part[(blockIdx.x*C + tid)*2]   = s1;
        d_part[(blockIdx.x*C + tid)*2+1] = s2;
    }
}

template<int C>
__global__ void bn_stats2(const float* __restrict__ gamma, const float* __restrict__ beta){
    int c = threadIdx.x;
    double s1 = 0.0, s2 = 0.0;
    for (int j=0;j<256;j++){
        s1 += (double)d_part[(j*C + c)*2];
        s2 += (double)d_part[(j*C + c)*2 + 1];
    }
    double mean = s1 / 65536.0;
    double var  = s2 / 65536.0 - mean*mean;
    float a = (float)((double)gamma[c] / sqrt(var + 1e-5));
    d_ab[c]       = a;
    d_ab[256 + c] = beta[c] - (float)mean * a;
}

// ---------------- final max over K ----------------
__global__ void maxk_kernel(float* __restrict__ out){
    int idx = blockIdx.x*256 + threadIdx.x;     // 1,048,576
    int o = idx & 255; int p = (idx >> 8) & 511; int b = idx >> 17;
    const float* Ob = d_O2 + ((b*NP + p)*KW)*256 + o;
    float m = -3.4e38f;
    #pragma unroll
    for (int k=0;k<16;k++) m = fmaxf(m, Ob[k*256]);
    out[4*3*BB*NP + (b*256 + o)*NP + p] = m;
}

// ---------------- launch ----------------
extern "C" void kernel_launch(void* const* d_in, const int* in_sizes, int n_in,
                              void* d_out, int out_size){
    const float* xyz   = (const float*)d_in[0];
    const float* nr    = (const float*)d_in[1];
    const float* Xa    = (const float*)d_in[2];
    const float* Ya    = (const float*)d_in[3];
    const float* pts   = (const float*)d_in[4];
    const float* w1_0  = (const float*)d_in[5];
    const float* b1_0  = (const float*)d_in[6];
    const float* w2_0  = (const float*)d_in[7];
    const float* b2_0  = (const float*)d_in[8];
    const float* bank0 = (const float*)d_in[9];
    const float* gam0  = (const float*)d_in[10];
    const float* bet0  = (const float*)d_in[11];
    const float* w1_1  = (const float*)d_in[12];
    const float* b1_1  = (const float*)d_in[13];
    const float* w2_1  = (const float*)d_in[14];
    const float* b2_1  = (const float*)d_in[15];
    const float* bank1 = (const float*)d_in[16];
    const float* gam1  = (const float*)d_in[17];
    const float* bet1  = (const float*)d_in[18];
    const float* w1_2  = (const float*)d_in[19];
    const float* b1_2  = (const float*)d_in[20];
    const float* w2_2  = (const float*)d_in[21];
    const float* b2_2  = (const float*)d_in[22];
    const float* bank2 = (const float*)d_in[23];
    float* out = (float*)d_out;

    float *pF0, *pO0, *pO1, *pO2, *pS, *pab;
    cudaGetSymbolAddress((void**)&pF0, d_F0);
    cudaGetSymbolAddress((void**)&pO0, d_O0);
    cudaGetSymbolAddress((void**)&pO1, d_O1);
    cudaGetSymbolAddress((void**)&pO2, d_O2);
    cudaGetSymbolAddress((void**)&pS,  d_S);
    cudaGetSymbolAddress((void**)&pab, d_ab);

    pp_kernel<<<64,256>>>(xyz);
    fps_kernel<<<8,256>>>(xyz, out);
    knn_kernel<<<512,256>>>(xyz);
    geom_kernel<<<512,128>>>(xyz, nr, Xa, Ya, pts, out);
    s_kernel<<<256,256>>>(w1_0,b1_0,w2_0,b2_0, w1_1,b1_1,w2_1,b2_1, w1_2,b1_2,w2_2,b2_2);

    paconv_gemm<64,64,false><<<dim3(1,1024),256>>>(pF0, pS,             bank0, pab, pO0);
    bn_stats1<64><<<256,256>>>(pO0);
    bn_stats2<64><<<1,64>>>(gam0, bet0);
    paconv_gemm<64,128,true><<<dim3(2,1024),256>>>(pO0, pS + ROWS*8,    bank1, pab, pO1);
    bn_stats1<128><<<256,256>>>(pO1);
    bn_stats2<128><<<1,128>>>(gam1, bet1);
    paconv_gemm<128,256,true><<<dim3(4,1024),256>>>(pO1, pS + 2*ROWS*8, bank2, pab, pO2);
    maxk_kernel<<<4096,256>>>(out);
}

// round 5
// speedup vs baseline: 1.4771x; 1.4771x over previous
#include <cuda_runtime.h>
#include <cuda_bf16.h>
#include <stdint.h>
#include <math.h>

#define BB 8
#define NN 2048
#define NP 512
#define KW 16
#define ROWS (BB*NP*KW)   // 65536

// ---------------- scratch (static device globals; no allocation) ----------------
__device__ int   d_fidx[BB*NP];
__device__ int   d_knn[ROWS];
__device__ float d_pp[BB*NN];
__device__ float d_geom[ROWS*10];
__device__ float d_S[3*ROWS*8];
__device__ float d_F0[ROWS*64];
__device__ float d_O0[ROWS*64];
__device__ float d_O1[ROWS*128];
__device__ float d_O2[ROWS*256];
__device__ float d_part[256*256*2];
__device__ float d_ab[512];
// pre-transposed + bf16-split banks: Bt[n][k], k = m*CIN + c
__device__ __nv_bfloat16 d_bh0[64*512],   d_bl0[64*512];
__device__ __nv_bfloat16 d_bh1[128*512],  d_bl1[128*512];
__device__ __nv_bfloat16 d_bh2[256*1024], d_bl2[256*1024];

// ---------------- point squared norms ----------------
__global__ void pp_kernel(const float* __restrict__ xyz){
    int i = blockIdx.x*256 + threadIdx.x;
    if (i < BB*NN){
        int b = i / NN, n = i % NN;
        const float* X = xyz + b*3*NN;
        float x = X[n], y = X[NN+n], z = X[2*NN+n];
        d_pp[i] = __fadd_rn(__fadd_rn(__fmul_rn(x,x),__fmul_rn(y,y)),__fmul_rn(z,z));
    }
}

// ---------------- farthest point sampling (one block per batch) ----------------
__global__ void fps_kernel(const float* __restrict__ xyz, float* __restrict__ out){
    int b = blockIdx.x, tid = threadIdx.x;
    __shared__ float sx[NN], sy[NN], sz[NN];
    __shared__ float swv[8]; __shared__ int swi[8];
    __shared__ int sfid[NP];
    const float* X = xyz + b*3*NN;
    for (int i = tid; i < NN; i += 256){ sx[i]=X[i]; sy[i]=X[NN+i]; sz[i]=X[2*NN+i]; }
    float dist[8];
    #pragma unroll
    for (int j=0;j<8;j++) dist[j] = 1e10f;
    __syncthreads();
    int far = 0;
    for (int it = 0; it < NP; ++it){
        if (tid == 0) sfid[it] = far;
        float cx = sx[far], cy = sy[far], cz = sz[far];
        float bv = -1.f; int bi = 0x7fffffff;
        #pragma unroll
        for (int j=0;j<8;j++){
            int n = j*256 + tid;
            float dx = __fsub_rn(sx[n],cx), dy = __fsub_rn(sy[n],cy), dz = __fsub_rn(sz[n],cz);
            float d  = __fadd_rn(__fadd_rn(__fmul_rn(dx,dx),__fmul_rn(dy,dy)),__fmul_rn(dz,dz));
            d = fminf(dist[j], d);
            dist[j] = d;
            if (d > bv) { bv = d; bi = n; }
        }
        #pragma unroll
        for (int off=16; off; off>>=1){
            float v2 = __shfl_down_sync(0xffffffffu, bv, off);
            int   i2 = __shfl_down_sync(0xffffffffu, bi, off);
            if (v2 > bv || (v2 == bv && i2 < bi)) { bv = v2; bi = i2; }
        }
        if ((tid & 31) == 0){ swv[tid>>5] = bv; swi[tid>>5] = bi; }
        __syncthreads();
        float fv = swv[0]; int fi = swi[0];
        #pragma unroll
        for (int w=1; w<8; w++){
            float v2 = swv[w]; int i2 = swi[w];
            if (v2 > fv || (v2 == fv && i2 < fi)) { fv = v2; fi = i2; }
        }
        far = fi;
        __syncthreads();
    }
    for (int p = tid; p < NP; p += 256){
        int n = sfid[p];
        d_fidx[b*NP + p] = n;
        out[(b*3+0)*NP + p] = sx[n];
        out[(b*3+1)*NP + p] = sy[n];
        out[(b*3+2)*NP + p] = sz[n];
    }
}

// ---------------- KNN: one warp per query, top-16 ascending (d, idx) ----------------
__global__ void knn_kernel(const float* __restrict__ xyz){
    int gw   = (blockIdx.x*blockDim.x + threadIdx.x) >> 5;
    int lane = threadIdx.x & 31;
    int b = gw >> 9, p = gw & 511;
    int qi = d_fidx[b*NP + p];
    const float* X = xyz + b*3*NN;
    float qx = X[qi], qy = X[NN+qi], qz = X[2*NN+qi];
    float qq = d_pp[b*NN + qi];
    float dk[16]; int ik[16];
    #pragma unroll
    for (int j=0;j<16;j++){ dk[j] = 3.4e38f; ik[j] = 0x7fffffff; }
    for (int c = 0; c < NN/32; c++){
        int n = c*32 + lane;
        float bx = X[n], by = X[NN+n], bz = X[2*NN+n];
        float d = (qq + d_pp[b*NN + n]) - 2.0f*(qx*bx + qy*by + qz*bz);
        bool acc = (d < dk[15]) || (d == dk[15] && n < ik[15]);
        if (acc){
            int pos = 0;
            #pragma unroll
            for (int j=0;j<16;j++) pos += ((dk[j] < d) || (dk[j] == d && ik[j] < n)) ? 1 : 0;
            #pragma unroll
            for (int j=15;j>=0;--j){
                if (j > pos){ dk[j] = dk[j-1]; ik[j] = ik[j-1]; }
                else if (j == pos){ dk[j] = d; ik[j] = n; }
            }
        }
    }
    for (int r = 0; r < 16; r++){
        float v = dk[0]; int i = ik[0];
        #pragma unroll
        for (int off=16; off; off>>=1){
            float v2 = __shfl_xor_sync(0xffffffffu, v, off);
            int   i2 = __shfl_xor_sync(0xffffffffu, i, off);
            if (v2 < v || (v2 == v && i2 < i)) { v = v2; i = i2; }
        }
        if (lane == 0) d_knn[gw*16 + r] = i;
        if (ik[0] == i){
            #pragma unroll
            for (int j=0;j<15;j++){ dk[j] = dk[j+1]; ik[j] = ik[j+1]; }
            dk[15] = 3.4e38f; ik[15] = 0x7fffffff;
        }
    }
}

// ---------------- geometry features + feat gather + norm/X/Y outputs ----------------
__global__ void geom_kernel(const float* __restrict__ xyz, const float* __restrict__ nr,
                            const float* __restrict__ Xa, const float* __restrict__ Ya,
                            const float* __restrict__ pts, float* out){
    int idx = blockIdx.x*128 + threadIdx.x;  // 65536 rows
    int b = idx >> 13;
    int p = (idx >> 4) & 511;
    int k = idx & 15;
    int n = d_knn[idx];
    int base = b*3*NN;
    float cx = out[(b*3+0)*NP + p], cy = out[(b*3+1)*NP + p], cz = out[(b*3+2)*NP + p];
    float gx = xyz[base+n] - cx, gy = xyz[base+NN+n] - cy, gz = xyz[base+2*NN+n] - cz;
    float nxv = nr[base+n], nyv = nr[base+NN+n], nzv = nr[base+2*NN+n];
    float Xx = Xa[base+n], Xy = Xa[base+NN+n], Xz = Xa[base+2*NN+n];
    float Yx = Ya[base+n], Yy = Ya[base+NN+n], Yz = Ya[base+2*NN+n];
    float dsq  = gx*gx + gy*gy + gz*gz;
    float dist = sqrtf(dsq + 1e-10f);
    float dmin = dist, dmax = dist;
    #pragma unroll
    for (int off=8; off; off>>=1){
        dmin = fminf(dmin, __shfl_xor_sync(0xffffffffu, dmin, off, 16));
        dmax = fmaxf(dmax, __shfl_xor_sync(0xffffffffu, dmax, off, 16));
    }
    float dn  = (dist - dmin) / ((dmax - dmin) + 1e-10f);
    float nn2 = sqrtf(gx*gx + gy*gy + gz*gz);
    const float INVPI = 0.318309886183790671f;
    float a0, a1, a2;
    {
        float dot = gx*nxv + gy*nyv + gz*nzv;
        float vn  = sqrtf(nxv*nxv + nyv*nyv + nzv*nzv);
        float c1  = dot / (nn2*vn + 1e-8f);
        a0 = acosf(fminf(1.f, fmaxf(-1.f, c1))) * INVPI;
    }
    {
        float dot = gx*Xx + gy*Xy + gz*Xz;
        float vn  = sqrtf(Xx*Xx + Xy*Xy + Xz*Xz);
        float c1  = dot / (nn2*vn + 1e-8f);
        a1 = acosf(fminf(1.f, fmaxf(-1.f, c1))) * INVPI;
    }
    {
        float dot = gx*Yx + gy*Yy + gz*Yz;
        float vn  = sqrtf(Yx*Yx + Yy*Yy + Yz*Yz);
        float c1  = dot / (nn2*vn + 1e-8f);
        a2 = acosf(fminf(1.f, fmaxf(-1.f, c1))) * INVPI;
    }
    float* g = d_geom + idx*10;
    g[0]=gx; g[1]=gy; g[2]=gz; g[3]=dn; g[4]=nxv; g[5]=nyv; g[6]=nzv; g[7]=a0; g[8]=a1; g[9]=a2;
    const float* P = pts + b*64*NN;
    float* F = d_F0 + idx*64;
    #pragma unroll 8
    for (int c=0;c<64;c++) F[c] = P[c*NN + n];
    if (k == 0){
        int o1 = 3*BB*NP;  // 12288
        out[1*o1 + (b*3+0)*NP+p] = nxv; out[1*o1 + (b*3+1)*NP+p] = nyv; out[1*o1 + (b*3+2)*NP+p] = nzv;
        out[2*o1 + (b*3+0)*NP+p] = Xx;  out[2*o1 + (b*3+1)*NP+p] = Xy;  out[2*o1 + (b*3+2)*NP+p] = Xz;
        out[3*o1 + (b*3+0)*NP+p] = Yx;  out[3*o1 + (b*3+1)*NP+p] = Yy;  out[3*o1 + (b*3+2)*NP+p] = Yz;
    }
}

// ---------------- scores s = softmax(w2 relu(w1 g + b1) + b2), all 3 layers ----------------
__global__ void s_kernel(const float* __restrict__ w1_0, const float* __restrict__ b1_0,
                         const float* __restrict__ w2_0, const float* __restrict__ b2_0,
                         const float* __restrict__ w1_1, const float* __restrict__ b1_1,
                         const float* __restrict__ w2_1, const float* __restrict__ b2_1,
                         const float* __restrict__ w1_2, const float* __restrict__ b1_2,
                         const float* __restrict__ w2_2, const float* __restrict__ b2_2){
    int idx = blockIdx.x*256 + threadIdx.x;
    float g[10];
    #pragma unroll
    for (int i=0;i<10;i++) g[i] = d_geom[idx*10 + i];
    const float* W1[3] = {w1_0, w1_1, w1_2};
    const float* B1[3] = {b1_0, b1_1, b1_2};
    const float* W2[3] = {w2_0, w2_1, w2_2};
    const float* B2[3] = {b2_0, b2_1, b2_2};
    #pragma unroll
    for (int l=0;l<3;l++){
        float h[16];
        #pragma unroll
        for (int j=0;j<16;j++){
            float acc = B1[l][j];
            #pragma unroll
            for (int q=0;q<10;q++) acc = fmaf(W1[l][j*10+q], g[q], acc);
            h[j] = fmaxf(acc, 0.f);
        }
        float t[8]; float mx = -3.4e38f;
        #pragma unroll
        for (int m=0;m<8;m++){
            float acc = B2[l][m];
            #pragma unroll
            for (int j=0;j<16;j++) acc = fmaf(W2[l][m*16+j], h[j], acc);
            t[m] = acc; mx = fmaxf(mx, acc);
        }
        float sum = 0.f;
        #pragma unroll
        for (int m=0;m<8;m++){ t[m] = expf(t[m] - mx); sum += t[m]; }
        float inv = 1.f / sum;
        #pragma unroll
        for (int m=0;m<8;m++) d_S[l*ROWS*8 + idx*8 + m] = t[m]*inv;
    }
}

// ---------------- bank transpose + bf16 split: Bt[n][k] ----------------
template<int CIN, int COUT>
__global__ void bsplit(const float* __restrict__ bank,
                       __nv_bfloat16* __restrict__ hi, __nv_bfloat16* __restrict__ lo){
    int i = blockIdx.x*256 + threadIdx.x;
    if (i < 8*CIN*COUT){
        int n = i % COUT; int k = i / COUT;
        float v = bank[i];
        __nv_bfloat16 h = __float2bfloat16_rn(v);
        __nv_bfloat16 l = __float2bfloat16_rn(v - __bfloat162float(h));
        hi[n*(8*CIN) + k] = h;
        lo[n*(8*CIN) + k] = l;
    }
}

// ---------------- split-bf16 mma.sync PAConv GEMM ----------------
// C[row,o] = sum_{m,c} s[row,m] * f(F[row,c]) * bank[m,c,o]
// CTA: 256 rows x 64 cols. 8 warps (4 row x 2 col), warp tile 64x32.
// K processed in chunks of 32, m-major (m outer so F tile stays hot in L1).
#define ASTR 36   // halfword row stride for SMEM tiles (conflict mitigation)

template<int CIN, int COUT, bool USE_BN>
__global__ void __launch_bounds__(256) paconv_mma(
        const float* __restrict__ F, const float* __restrict__ S,
        const __nv_bfloat16* __restrict__ Bth, const __nv_bfloat16* __restrict__ Btl,
        const float* __restrict__ ab, float* __restrict__ O)
{
    constexpr int KTOT = 8*CIN;
    __shared__ __nv_bfloat16 Ah[256*ASTR], Al[256*ASTR];
    __shared__ __nv_bfloat16 Bh[64*ASTR],  Bl[64*ASTR];
    __shared__ float bnA[CIN], bnB[CIN];

    int tid = threadIdx.x;
    int wid = tid >> 5, lane = tid & 31;
    int wr = wid & 3;        // warp row group: rows wr*64 .. wr*64+63
    int wc = wid >> 2;       // warp col group: cols wc*32 .. wc*32+31
    int row0 = blockIdx.x * 256;
    int col0 = blockIdx.y * 64;

    if (USE_BN){
        for (int i = tid; i < CIN; i += 256){ bnA[i] = ab[i]; bnB[i] = ab[256+i]; }
    }

    float sv[8];
    {
        const float* Sp = S + (size_t)(row0 + tid)*8;
        #pragma unroll
        for (int m=0;m<8;m++) sv[m] = Sp[m];
    }
    const float* Fp = F + (size_t)(row0 + tid)*CIN;

    float acc[4][4][4];
    #pragma unroll
    for (int i=0;i<4;i++)
        #pragma unroll
        for (int j=0;j<4;j++)
            #pragma unroll
            for (int q=0;q<4;q++) acc[i][j][q] = 0.f;

    int gr = lane >> 2;          // group row 0..7
    int qc = (lane & 3) * 2;     // pair col base

    for (int c0 = 0; c0 < CIN; c0 += 32){
        #pragma unroll 1
        for (int m = 0; m < 8; m++){
            __syncthreads();
            // ---- A fill: thread tid owns row tid ----
            {
                float s = sv[m];
                const float4* src = (const float4*)(Fp + c0);
                #pragma unroll
                for (int j=0;j<8;j++){
                    float4 v = src[j];
                    if (USE_BN){
                        float4 a4 = *(const float4*)(bnA + c0 + 4*j);
                        float4 b4 = *(const float4*)(bnB + c0 + 4*j);
                        v.x = fmaxf(fmaf(v.x, a4.x, b4.x), 0.f);
                        v.y = fmaxf(fmaf(v.y, a4.y, b4.y), 0.f);
                        v.z = fmaxf(fmaf(v.z, a4.z, b4.z), 0.f);
                        v.w = fmaxf(fmaf(v.w, a4.w, b4.w), 0.f);
                    }
                    v.x *= s; v.y *= s; v.z *= s; v.w *= s;
                    __nv_bfloat162 h01 = __floats2bfloat162_rn(v.x, v.y);
                    __nv_bfloat162 h23 = __floats2bfloat162_rn(v.z, v.w);
                    __nv_bfloat162 l01 = __floats2bfloat162_rn(
                        v.x - __bfloat162float(__low2bfloat16(h01)),
                        v.y - __bfloat162float(__high2bfloat16(h01)));
                    __nv_bfloat162 l23 = __floats2bfloat162_rn(
                        v.z - __bfloat162float(__low2bfloat16(h23)),
                        v.w - __bfloat162float(__high2bfloat16(h23)));
                    int off = tid*ASTR + j*4;
                    *(__nv_bfloat162*)&Ah[off]   = h01;
                    *(__nv_bfloat162*)&Ah[off+2] = h23;
                    *(__nv_bfloat162*)&Al[off]   = l01;
                    *(__nv_bfloat162*)&Al[off+2] = l23;
                }
            }
            // ---- B fill: 64 n x 32 k (8 bf16 per thread = 2x uint2, 8B-aligned) ----
            {
                int n = tid >> 2, g = tid & 3;
                size_t gb = (size_t)(col0 + n)*KTOT + m*CIN + c0 + g*8;
                uint2 hv0 = *(const uint2*)(Bth + gb);
                uint2 hv1 = *(const uint2*)(Bth + gb + 4);
                uint2 lv0 = *(const uint2*)(Btl + gb);
                uint2 lv1 = *(const uint2*)(Btl + gb + 4);
                *(uint2*)&Bh[n*ASTR + g*8]     = hv0;
                *(uint2*)&Bh[n*ASTR + g*8 + 4] = hv1;
                *(uint2*)&Bl[n*ASTR + g*8]     = lv0;
                *(uint2*)&Bl[n*ASTR + g*8 + 4] = lv1;
            }
            __syncthreads();
            // ---- MMA over the 32-wide chunk (2 x k16) ----
            #pragma unroll
            for (int kb = 0; kb < 32; kb += 16){
                uint32_t ah[4][4], al[4][4], bh[4][2], bl[4][2];
                #pragma unroll
                for (int mt=0; mt<4; mt++){
                    int r = wr*64 + mt*16 + gr;
                    ah[mt][0] = *(const uint32_t*)&Ah[ r   *ASTR + kb + qc];
                    ah[mt][1] = *(const uint32_t*)&Ah[(r+8)*ASTR + kb + qc];
                    ah[mt][2] = *(const uint32_t*)&Ah[ r   *ASTR + kb + qc + 8];
                    ah[mt][3] = *(const uint32_t*)&Ah[(r+8)*ASTR + kb + qc + 8];
                    al[mt][0] = *(const uint32_t*)&Al[ r   *ASTR + kb + qc];
                    al[mt][1] = *(const uint32_t*)&Al[(r+8)*ASTR + kb + qc];
                    al[mt][2] = *(const uint32_t*)&Al[ r   *ASTR + kb + qc + 8];
                    al[mt][3] = *(const uint32_t*)&Al[(r+8)*ASTR + kb + qc + 8];
                }
                #pragma unroll
                for (int nt=0; nt<4; nt++){
                    int n = wc*32 + nt*8 + gr;
                    bh[nt][0] = *(const uint32_t*)&Bh[n*ASTR + kb + qc];
                    bh[nt][1] = *(const uint32_t*)&Bh[n*ASTR + kb + qc + 8];
                    bl[nt][0] = *(const uint32_t*)&Bl[n*ASTR + kb + qc];
                    bl[nt][1] = *(const uint32_t*)&Bl[n*ASTR + kb + qc + 8];
                }
                #pragma unroll
                for (int mt=0; mt<4; mt++)
                    #pragma unroll
                    for (int nt=0; nt<4; nt++){
                        float* d = acc[mt][nt];
                        asm volatile(
                          "mma.sync.aligned.m16n8k16.row.col.f32.bf16.bf16.f32 "
                          "{%0,%1,%2,%3}, {%4,%5,%6,%7}, {%8,%9}, {%0,%1,%2,%3};"
                          : "+f"(d[0]),"+f"(d[1]),"+f"(d[2]),"+f"(d[3])
                          : "r"(ah[mt][0]),"r"(ah[mt][1]),"r"(ah[mt][2]),"r"(ah[mt][3]),
                            "r"(bh[nt][0]),"r"(bh[nt][1]));
                        asm volatile(
                          "mma.sync.aligned.m16n8k16.row.col.f32.bf16.bf16.f32 "
                          "{%0,%1,%2,%3}, {%4,%5,%6,%7}, {%8,%9}, {%0,%1,%2,%3};"
                          : "+f"(d[0]),"+f"(d[1]),"+f"(d[2]),"+f"(d[3])
                          : "r"(ah[mt][0]),"r"(ah[mt][1]),"r"(ah[mt][2]),"r"(ah[mt][3]),
                            "r"(bl[nt][0]),"r"(bl[nt][1]));
                        asm volatile(
                          "mma.sync.aligned.m16n8k16.row.col.f32.bf16.bf16.f32 "
                          "{%0,%1,%2,%3}, {%4,%5,%6,%7}, {%8,%9}, {%0,%1,%2,%3};"
                          : "+f"(d[0]),"+f"(d[1]),"+f"(d[2]),"+f"(d[3])
                          : "r"(al[mt][0]),"r"(al[mt][1]),"r"(al[mt][2]),"r"(al[mt][3]),
                            "r"(bh[nt][0]),"r"(bh[nt][1]));
                    }
            }
        }
    }

    // ---- epilogue: direct stores ----
    #pragma unroll
    for (int mt=0; mt<4; mt++){
        int r = row0 + wr*64 + mt*16 + gr;
        #pragma unroll
        for (int nt=0; nt<4; nt++){
            int c = col0 + wc*32 + nt*8 + qc;
            float* d = acc[mt][nt];
            *(float2*)&O[(size_t)r*COUT + c]     = make_float2(d[0], d[1]);
            *(float2*)&O[(size_t)(r+8)*COUT + c] = make_float2(d[2], d[3]);
        }
    }
}

// ---------------- BN stats: deterministic two-stage ----------------
template<int C>
__global__ void bn_stats1(const float* __restrict__ O){
    __shared__ float sm1[256], sm2[256];
    int tid = threadIdx.x;
    float s1 = 0.f, s2 = 0.f;
    for (int i = blockIdx.x*256 + tid; i < ROWS*C; i += 65536){
        float v = O[i]; s1 += v; s2 += v*v;
    }
    sm1[tid] = s1; sm2[tid] = s2; __syncthreads();
    if (tid < C){
        for (int j = tid + C; j < 256; j += C){ s1 += sm1[j]; s2 += sm2[j]; }
        d_part[(blockIdx.x*C + tid)*2]   = s1;
        d_part[(blockIdx.x*C + tid)*2+1] = s2;
    }
}

template<int C>
__global__ void bn_stats2(const float* __restrict__ gamma, const float* __restrict__ beta){
    int c = threadIdx.x;
    double s1 = 0.0, s2 = 0.0;
    for (int j=0;j<256;j++){
        s1 += (double)d_part[(j*C + c)*2];
        s2 += (double)d_part[(j*C + c)*2 + 1];
    }
    double mean = s1 / 65536.0;
    double var  = s2 / 65536.0 - mean*mean;
    float a = (float)((double)gamma[c] / sqrt(var + 1e-5));
    d_ab[c]       = a;
    d_ab[256 + c] = beta[c] - (float)mean * a;
}

// ---------------- final max over K ----------------
__global__ void maxk_kernel(float* __restrict__ out){
    int idx = blockIdx.x*256 + threadIdx.x;
    int o = idx & 255; int p = (idx >> 8) & 511; int b = idx >> 17;
    const float* Ob = d_O2 + ((size_t)(b*NP + p)*KW)*256 + o;
    float m = -3.4e38f;
    #pragma unroll
    for (int k=0;k<16;k++) m = fmaxf(m, Ob[k*256]);
    out[4*3*BB*NP + (b*256 + o)*NP + p] = m;
}

// ---------------- launch ----------------
extern "C" void kernel_launch(void* const* d_in, const int* in_sizes, int n_in,
                              void* d_out, int out_size){
    const float* xyz   = (const float*)d_in[0];
    const float* nr    = (const float*)d_in[1];
    const float* Xa    = (const float*)d_in[2];
    const float* Ya    = (const float*)d_in[3];
    const float* pts   = (const float*)d_in[4];
    const float* w1_0  = (const float*)d_in[5];
    const float* b1_0  = (const float*)d_in[6];
    const float* w2_0  = (const float*)d_in[7];
    const float* b2_0  = (const float*)d_in[8];
    const float* bank0 = (const float*)d_in[9];
    const float* gam0  = (const float*)d_in[10];
    const float* bet0  = (const float*)d_in[11];
    const float* w1_1  = (const float*)d_in[12];
    const float* b1_1  = (const float*)d_in[13];
    const float* w2_1  = (const float*)d_in[14];
    const float* b2_1  = (const float*)d_in[15];
    const float* bank1 = (const float*)d_in[16];
    const float* gam1  = (const float*)d_in[17];
    const float* bet1  = (const float*)d_in[18];
    const float* w1_2  = (const float*)d_in[19];
    const float* b1_2  = (const float*)d_in[20];
    const float* w2_2  = (const float*)d_in[21];
    const float* b2_2  = (const float*)d_in[22];
    const float* bank2 = (const float*)d_in[23];
    float* out = (float*)d_out;

    float *pF0, *pO0, *pO1, *pO2, *pS, *pab;
    __nv_bfloat16 *pBH0, *pBL0, *pBH1, *pBL1, *pBH2, *pBL2;
    cudaGetSymbolAddress((void**)&pF0, d_F0);
    cudaGetSymbolAddress((void**)&pO0, d_O0);
    cudaGetSymbolAddress((void**)&pO1, d_O1);
    cudaGetSymbolAddress((void**)&pO2, d_O2);
    cudaGetSymbolAddress((void**)&pS,  d_S);
    cudaGetSymbolAddress((void**)&pab, d_ab);
    cudaGetSymbolAddress((void**)&pBH0, d_bh0);
    cudaGetSymbolAddress((void**)&pBL0, d_bl0);
    cudaGetSymbolAddress((void**)&pBH1, d_bh1);
    cudaGetSymbolAddress((void**)&pBL1, d_bl1);
    cudaGetSymbolAddress((void**)&pBH2, d_bh2);
    cudaGetSymbolAddress((void**)&pBL2, d_bl2);

    pp_kernel<<<64,256>>>(xyz);
    bsplit<64,64><<<128,256>>>(bank0, pBH0, pBL0);
    bsplit<64,128><<<256,256>>>(bank1, pBH1, pBL1);
    bsplit<128,256><<<1024,256>>>(bank2, pBH2, pBL2);
    fps_kernel<<<8,256>>>(xyz, out);
    knn_kernel<<<512,256>>>(xyz);
    geom_kernel<<<512,128>>>(xyz, nr, Xa, Ya, pts, out);
    s_kernel<<<256,256>>>(w1_0,b1_0,w2_0,b2_0, w1_1,b1_1,w2_1,b2_1, w1_2,b1_2,w2_2,b2_2);

    paconv_mma<64,64,false><<<dim3(256,1),256>>>(pF0, pS,             pBH0, pBL0, pab, pO0);
    bn_stats1<64><<<256,256>>>(pO0);
    bn_stats2<64><<<1,64>>>(gam0, bet0);
    paconv_mma<64,128,true><<<dim3(256,2),256>>>(pO0, pS + ROWS*8,    pBH1, pBL1, pab, pO1);
    bn_stats1<128><<<256,256>>>(pO1);
    bn_stats2<128><<<1,128>>>(gam1, bet1);
    paconv_mma<128,256,true><<<dim3(256,4),256>>>(pO1, pS + 2*ROWS*8, pBH2, pBL2, pab, pO2);
    maxk_kernel<<<4096,256>>>(out);
}